// round 1
// baseline (speedup 1.0000x reference)
#include <cuda_runtime.h>

// Problem constants
#define B_ 8
#define V_ 49
#define H_ 128
#define W_ 128
#define F_ 64

#define NROWS (B_ * V_ * H_)        // 50176 rows of the output [B,V,H,·]
#define MASK_ELEMS (B_ * H_ * F_)   // 65536

// Scratch: transposed + prescaled mask, mask_t[b][h][f] = W * h_mask[b][f][h]
__device__ float g_mask_t[MASK_ELEMS];

// Stage 1: tiny transpose+scale of h_mask (256 KB each way; negligible)
__global__ void mask_transpose_kernel(const float* __restrict__ h_mask) {
    int idx = blockIdx.x * blockDim.x + threadIdx.x;   // over B*H*F
    if (idx < MASK_ELEMS) {
        int f = idx % F_;
        int h = (idx / F_) % H_;
        int b = idx / (F_ * H_);
        g_mask_t[idx] = (float)W_ * h_mask[(b * F_ + f) * H_ + h];
    }
}

// Stage 2: one warp per (b,v,h) row.
//   lane loads 1 float4 of lfi (32 lanes x 16B = full 512B row, coalesced)
//   butterfly-reduce row sum
//   lane writes 1 float2 of out (32 lanes x 8B = full 256B row, coalesced)
__global__ void __launch_bounds__(256, 8)
depth_cue_kernel(const float4* __restrict__ lfi4, float2* __restrict__ out2) {
    int gtid = blockIdx.x * blockDim.x + threadIdx.x;
    int warp = gtid >> 5;            // row index in [0, NROWS) — grid sized exactly
    int lane = threadIdx.x & 31;

    // Row sum of lfi[b,v,h,:]
    float4 v4 = lfi4[(long long)warp * 32 + lane];
    float s = (v4.x + v4.y) + (v4.z + v4.w);
    #pragma unroll
    for (int o = 16; o > 0; o >>= 1)
        s += __shfl_xor_sync(0xffffffffu, s, o);

    // Decode b, h from row index (layout [B,V,H])
    int h = warp % H_;
    int b = warp / (V_ * H_);

    // Coalesced contiguous mask read (L2-resident) + coalesced output write
    const float2* __restrict__ m2 =
        (const float2*)(g_mask_t + (b * H_ + h) * F_);
    float2 m = m2[lane];
    out2[(long long)warp * 32 + lane] = make_float2(s + m.x, s + m.y);
}

extern "C" void kernel_launch(void* const* d_in, const int* in_sizes, int n_in,
                              void* d_out, int out_size) {
    // Identify inputs by element count (robust to ordering):
    //   lfi    : B*V*H*W = 6,422,528
    //   f_maps : B*H*W*F = 8,388,608 (unused)
    //   h_mask : B*F*H   = 65,536
    const float* lfi = nullptr;
    const float* h_mask = nullptr;
    for (int i = 0; i < n_in; i++) {
        if (in_sizes[i] == B_ * V_ * H_ * W_) lfi = (const float*)d_in[i];
        else if (in_sizes[i] == B_ * F_ * H_) h_mask = (const float*)d_in[i];
    }

    // Stage 1: mask transpose (65536 elems / 256 = 256 blocks)
    mask_transpose_kernel<<<MASK_ELEMS / 256, 256>>>(h_mask);

    // Stage 2: 50176 warps, 8 warps per block -> 6272 blocks (exact)
    depth_cue_kernel<<<NROWS / 8, 256>>>((const float4*)lfi, (float2*)d_out);
}

// round 2
// speedup vs baseline: 1.0313x; 1.0313x over previous
#include <cuda_runtime.h>

// Problem constants
#define B_ 8
#define V_ 49
#define H_ 128
#define W_ 128
#define F_ 64

#define NROWS (B_ * V_ * H_)        // 50176 rows of the output [B,V,H,·]
#define MASK_ELEMS (B_ * H_ * F_)   // 65536
#define ROWS_PER_WARP 4

// Scratch: transposed + prescaled mask, mask_t[b][h][f] = W * h_mask[b][f][h]
__device__ float g_mask_t[MASK_ELEMS];

// Stage 1: tiny transpose+scale of h_mask (256 KB each way; negligible)
__global__ void mask_transpose_kernel(const float* __restrict__ h_mask) {
    int idx = blockIdx.x * blockDim.x + threadIdx.x;   // over B*H*F
    if (idx < MASK_ELEMS) {
        int f = idx % F_;
        int h = (idx / F_) % H_;
        int b = idx / (F_ * H_);
        g_mask_t[idx] = (float)W_ * h_mask[(b * F_ + f) * H_ + h];
    }
}

// Stage 2: 4 rows per warp for ILP.
//   Per row: lane loads 1 float4 of lfi (coalesced 512B), butterfly-reduce,
//   lane writes 1 float2 of out (coalesced 256B).
//   The 4 rows give 4 independent load->shuffle-chain->store streams, hiding
//   the ~130-cycle dependent SHFL latency that bound round 1.
__global__ void __launch_bounds__(256, 8)
depth_cue_kernel(const float4* __restrict__ lfi4, float2* __restrict__ out2) {
    int gtid = blockIdx.x * blockDim.x + threadIdx.x;
    int warp = gtid >> 5;                     // in [0, NROWS/ROWS_PER_WARP)
    int lane = threadIdx.x & 31;
    int row0 = warp * ROWS_PER_WARP;

    // Front-batched independent loads (MLP = 4)
    float s[ROWS_PER_WARP];
    #pragma unroll
    for (int r = 0; r < ROWS_PER_WARP; r++) {
        float4 v = lfi4[(long long)(row0 + r) * 32 + lane];
        s[r] = (v.x + v.y) + (v.z + v.w);
    }

    // 4 interleaved independent butterfly reductions
    #pragma unroll
    for (int o = 16; o > 0; o >>= 1) {
        #pragma unroll
        for (int r = 0; r < ROWS_PER_WARP; r++)
            s[r] += __shfl_xor_sync(0xffffffffu, s[r], o);
    }

    // Mask add + coalesced stores (4 independent streams)
    #pragma unroll
    for (int r = 0; r < ROWS_PER_WARP; r++) {
        int row = row0 + r;
        int h = row % H_;                     // layout [B,V,H]
        int b = row / (V_ * H_);
        float2 m = ((const float2*)(g_mask_t + (b * H_ + h) * F_))[lane];
        out2[(long long)row * 32 + lane] = make_float2(s[r] + m.x, s[r] + m.y);
    }
}

extern "C" void kernel_launch(void* const* d_in, const int* in_sizes, int n_in,
                              void* d_out, int out_size) {
    // Identify inputs by element count (robust to ordering):
    //   lfi    : B*V*H*W = 6,422,528
    //   f_maps : B*H*W*F = 8,388,608 (unused — never touched)
    //   h_mask : B*F*H   = 65,536
    const float* lfi = nullptr;
    const float* h_mask = nullptr;
    for (int i = 0; i < n_in; i++) {
        if (in_sizes[i] == B_ * V_ * H_ * W_) lfi = (const float*)d_in[i];
        else if (in_sizes[i] == B_ * F_ * H_) h_mask = (const float*)d_in[i];
    }

    // Stage 1: mask transpose (65536 elems / 256 = 256 blocks)
    mask_transpose_kernel<<<MASK_ELEMS / 256, 256>>>(h_mask);

    // Stage 2: 50176 rows / 4 rows-per-warp = 12544 warps; 8 warps/block = 1568 blocks (exact)
    depth_cue_kernel<<<NROWS / (ROWS_PER_WARP * 8), 256>>>((const float4*)lfi, (float2*)d_out);
}

// round 3
// speedup vs baseline: 1.1792x; 1.1434x over previous
#include <cuda_runtime.h>

// Problem constants
#define B_ 8
#define V_ 49
#define H_ 128
#define W_ 128
#define F_ 64

// out[b,v,h,f] = sum_w lfi[b,v,h,w] + W * h_mask[b,f,h]
//
// Block = one (b,h) pair: 1024 blocks, 224 threads (7 warps).
//   - mask row (64 floats, scattered stride-512B gather) loaded ONCE per block
//     into smem, reused by all 49 rows of this (b,h).
//   - warp w handles v = 7w .. 7w+6: 7 coalesced float4 loads (ILP=7),
//     7 interleaved butterfly reductions, 7 coalesced float2 stores.
//   - 1024 blocks at 7 blocks/SM = exactly one wave on 148 SMs.
__global__ void __launch_bounds__(224, 7)
depth_cue_kernel(const float4* __restrict__ lfi4,
                 const float* __restrict__ h_mask,
                 float2* __restrict__ out2) {
    __shared__ float m_s[F_];

    int pair = blockIdx.x;          // b*128 + h
    int b = pair >> 7;
    int h = pair & (H_ - 1);
    int tid = threadIdx.x;
    int wid = tid >> 5;
    int lane = tid & 31;

    // One-time scattered mask gather: m_s[f] = W * h_mask[b,f,h]
    if (tid < F_) {
        m_s[tid] = (float)W_ * h_mask[((b << 6) + tid) * H_ + h];
    }
    __syncthreads();

    // Rows for this warp: row(r) = (b*49 + 7*wid + r)*128 + h
    long long row0 = (long long)(b * V_ + wid * 7) * H_ + h;

    // Front-batched independent coalesced loads (512B per row per warp)
    float s[7];
    #pragma unroll
    for (int r = 0; r < 7; r++) {
        float4 v = lfi4[(row0 + (long long)r * H_) * 32 + lane];
        s[r] = (v.x + v.y) + (v.z + v.w);
    }

    // 7 interleaved butterfly reductions: SHFL latency hidden 7-deep
    #pragma unroll
    for (int o = 16; o > 0; o >>= 1) {
        #pragma unroll
        for (int r = 0; r < 7; r++)
            s[r] += __shfl_xor_sync(0xffffffffu, s[r], o);
    }

    // Broadcast mask from smem (conflict-free), coalesced float2 stores
    float2 m = ((const float2*)m_s)[lane];
    #pragma unroll
    for (int r = 0; r < 7; r++) {
        out2[(row0 + (long long)r * H_) * 32 + lane] =
            make_float2(s[r] + m.x, s[r] + m.y);
    }
}

extern "C" void kernel_launch(void* const* d_in, const int* in_sizes, int n_in,
                              void* d_out, int out_size) {
    // Identify inputs by element count (robust to ordering):
    //   lfi    : B*V*H*W = 6,422,528
    //   f_maps : B*H*W*F = 8,388,608 (dead input — never touched)
    //   h_mask : B*F*H   = 65,536
    const float* lfi = nullptr;
    const float* h_mask = nullptr;
    for (int i = 0; i < n_in; i++) {
        if (in_sizes[i] == B_ * V_ * H_ * W_) lfi = (const float*)d_in[i];
        else if (in_sizes[i] == B_ * F_ * H_) h_mask = (const float*)d_in[i];
    }

    // 1024 blocks (one per (b,h) pair), 224 threads (7 warps x 7 rows = 49 = V)
    depth_cue_kernel<<<B_ * H_, 224>>>((const float4*)lfi, h_mask, (float2*)d_out);
}

// round 4
// speedup vs baseline: 1.2462x; 1.0568x over previous
#include <cuda_runtime.h>

// Problem constants
#define B_ 8
#define V_ 49
#define H_ 128
#define W_ 128
#define F_ 64

// out[b,v,h,f] = sum_w lfi[b,v,h,w] + W * h_mask[b,f,h]
//
// Block = one (b,h) pair: 1024 blocks, 224 threads (7 warps x 7 rows).
// Key ordering (vs round 3): mask gather issues FIRST, then all 7 lfi loads
// are in flight BEFORE any barrier. The __syncthreads (needed only for the
// smem mask) is deferred until after the butterfly reduce, so it overlaps the
// DRAM latency instead of serializing the block prologue.
__global__ void __launch_bounds__(224, 7)
depth_cue_kernel(const float4* __restrict__ lfi4,
                 const float* __restrict__ h_mask,
                 float2* __restrict__ out2) {
    __shared__ float m_s[F_];

    int pair = blockIdx.x;          // b*128 + h
    int b = pair >> 7;
    int h = pair & (H_ - 1);
    int tid = threadIdx.x;
    int wid = tid >> 5;
    int lane = tid & 31;

    // 1) Scattered mask gather (warps 0,1 only): m = W * h_mask[b,f,h].
    //    Issued before everything else so it overlaps the lfi loads.
    float mval = 0.0f;
    if (tid < F_) {
        mval = (float)W_ * __ldg(&h_mask[((b << 6) + tid) * H_ + h]);
    }

    // 2) Front-batched independent coalesced lfi loads (true MLP = 7; the
    //    41-reg budget at occupancy 7 holds all 7 LDG.128 dests live).
    long long row0 = (long long)(b * V_ + wid * 7) * H_ + h;
    float s[7];
    #pragma unroll
    for (int r = 0; r < 7; r++) {
        float4 v = lfi4[(row0 + (long long)r * H_) * 32 + lane];
        s[r] = (v.x + v.y) + (v.z + v.w);
    }

    // 3) Park the mask in smem (fire-and-forget STS; waits only on warps 0,1's
    //    own gather, overlapped with other warps' reduce).
    if (tid < F_) m_s[tid] = mval;

    // 4) 7 interleaved butterfly reductions (SHFL latency hidden 7-deep)
    #pragma unroll
    for (int o = 16; o > 0; o >>= 1) {
        #pragma unroll
        for (int r = 0; r < 7; r++)
            s[r] += __shfl_xor_sync(0xffffffffu, s[r], o);
    }

    // 5) Barrier AFTER all latency is already absorbed
    __syncthreads();

    // 6) Broadcast mask from smem, coalesced float2 stores (7 streams)
    float2 m = ((const float2*)m_s)[lane];
    #pragma unroll
    for (int r = 0; r < 7; r++) {
        out2[(row0 + (long long)r * H_) * 32 + lane] =
            make_float2(s[r] + m.x, s[r] + m.y);
    }
}

extern "C" void kernel_launch(void* const* d_in, const int* in_sizes, int n_in,
                              void* d_out, int out_size) {
    // Identify inputs by element count (robust to ordering):
    //   lfi    : B*V*H*W = 6,422,528
    //   f_maps : B*H*W*F = 8,388,608 (dead input — never touched)
    //   h_mask : B*F*H   = 65,536
    const float* lfi = nullptr;
    const float* h_mask = nullptr;
    for (int i = 0; i < n_in; i++) {
        if (in_sizes[i] == B_ * V_ * H_ * W_) lfi = (const float*)d_in[i];
        else if (in_sizes[i] == B_ * F_ * H_) h_mask = (const float*)d_in[i];
    }

    // 1024 blocks (one per (b,h) pair), 224 threads (7 warps x 7 rows = 49 = V)
    depth_cue_kernel<<<B_ * H_, 224>>>((const float4*)lfi, h_mask, (float2*)d_out);
}